// round 10
// baseline (speedup 1.0000x reference)
#include <cuda_runtime.h>
#include <math.h>

#define T_STEPS 32
#define N_BATCH 16
#define D_DIM   256
#define A_DIM   256
#define F1_DIM  512
#define F2_DIM  256
#define BK 16

// Scratch (allocation-free rule: __device__ globals)
__device__ float g_s2[T_STEPS * N_BATCH * D_DIM];    // [T,N,D]   512KB
__device__ float g_h1[T_STEPS * N_BATCH * F1_DIM];   // [T,N,F1]  1MB
__device__ float g_part[9 * 256 * 1024];             // split-K partials, 9MB

// ---------------------------------------------------------------------------
// K1: fused SDC-linear + exp-filter + LIF + synapse-filter + pool + s2-LIF.
// (unchanged from R9 — measured good)
// ---------------------------------------------------------------------------
__global__ void __launch_bounds__(256) k_snn_core(
    const float* __restrict__ x,      // [T,N,2,D]
    const float* __restrict__ W_sdc,  // [2,A]
    const float* __restrict__ b_sdc,  // [A]
    const float* __restrict__ w_syn,  // [1]
    const float* __restrict__ W_pool, // [A,1]
    const float* __restrict__ b_pool) // [1]
{
    const int a    = threadIdx.x;
    const int nd   = blockIdx.x;
    const int n    = nd >> 8;   // D = 256
    const int d    = nd & 255;
    const int lane = a & 31;
    const int warp = a >> 5;

    const float w0 = W_sdc[a];
    const float w1 = W_sdc[A_DIM + a];
    const float ba = b_sdc[a];
    const float wp = W_pool[a];
    const float dsyn = 1.0f - 1.0f / (1.0f + expf(-w_syn[0]));
    const float bp = b_pool[0];

    float i_s = 0.0f, v = 0.0f, syn = 0.0f;

    __shared__ float sh[T_STEPS][137];   // stride 137: conflict-free both phases

    #pragma unroll 4
    for (int t = 0; t < T_STEPS; ++t) {
        const float x0 = x[((t * N_BATCH + n) * 2 + 0) * D_DIM + d];
        const float x1 = x[((t * N_BATCH + n) * 2 + 1) * D_DIM + d];
        const float h  = fmaf(x0, w0, fmaf(x1, w1, ba));

        i_s = fmaf(i_s, 0.5f, h);                     // exp_filter tau=2
        v = fmaf(i_s - v, 0.5f, v);                   // LIF tau=2
        const float s1 = (v >= 1.0f) ? 1.0f : 0.0f;
        v = (s1 != 0.0f) ? 0.0f : v;
        syn = fmaf(syn, dsyn, s1);                    // synapse filter

        float val = syn * wp;
        val += __shfl_down_sync(0xffffffffu, val, 16);
        if (lane < 16) sh[t][(warp << 4) + lane] = val;   // 16 partials/warp
    }
    __syncthreads();

    if (warp == 0) {
        float z0 = 0.0f, z1 = 0.0f, z2 = 0.0f, z3 = 0.0f;
        #pragma unroll
        for (int j = 0; j < 128; j += 4) {
            z0 += sh[lane][j + 0];
            z1 += sh[lane][j + 1];
            z2 += sh[lane][j + 2];
            z3 += sh[lane][j + 3];
        }
        float z = bp + ((z0 + z1) + (z2 + z3));

        float v2 = 0.0f, s_mine = 0.0f;
        #pragma unroll
        for (int t = 0; t < T_STEPS; ++t) {
            const float zt = __shfl_sync(0xffffffffu, z, t);
            v2 = fmaf(zt - v2, 0.5f, v2);
            const float s = (v2 >= 1.0f) ? 1.0f : 0.0f;
            v2 = (s != 0.0f) ? 0.0f : v2;
            if (lane == t) s_mine = s;
        }
        g_s2[(lane * N_BATCH + n) * D_DIM + d] = s_mine;
    }
}

// ---------------------------------------------------------------------------
// Split-K SGEMM, 128x64 tile, BK=16, 256 threads, 8x4 micro-tile.
// Per kk: 3 LDS.128 (2 broadcast A + 1 conflict-free B) per 32 FMA ->
// FMA-bound instead of smem-BW-bound. Global->reg prefetch. Deterministic.
// ---------------------------------------------------------------------------
__global__ void __launch_bounds__(256) k_gemm_splitk(
    const float* __restrict__ A, const float* __restrict__ B,
    float* __restrict__ P, int M, int K, int N, int Kc)
{
    __shared__ float As[BK][132];  // [k][m], 128 + pad 4 (132*4B = 16B-aligned rows)
    __shared__ float Bs[BK][64];   // [k][n]
    const int tid = threadIdx.x;
    const int tx  = tid & 15;      // col group (4 cols): 16*4 = 64
    const int ty  = tid >> 4;      // row group (8 rows): 16*8 = 128
    const int row0 = blockIdx.y * 128;
    const int col0 = blockIdx.x * 64;
    const int kbeg = blockIdx.z * Kc;
    const int kend = kbeg + Kc;

    // A: 128 rows x 16 k = 2048 floats -> 2 float4 / thread
    const int ar = tid >> 1;             // 0..127 : A row
    const int ak = (tid & 1) << 3;       // 0 or 8 : A k-seg (8 floats)
    // B: 16 k x 64 n = 1024 floats -> 1 float4 / thread
    const int bk = tid >> 4;             // 0..15 : B k row
    const int bn = (tid & 15) << 2;      // B col seg (4)

    float acc[8][4] = {};

    float4 a0 = *(const float4*)(A + (row0 + ar) * K + kbeg + ak);
    float4 a1 = *(const float4*)(A + (row0 + ar) * K + kbeg + ak + 4);
    float4 bv = *(const float4*)(B + (kbeg + bk) * N + col0 + bn);

    for (int k0 = kbeg; k0 < kend; k0 += BK) {
        As[ak + 0][ar] = a0.x;  As[ak + 1][ar] = a0.y;
        As[ak + 2][ar] = a0.z;  As[ak + 3][ar] = a0.w;
        As[ak + 4][ar] = a1.x;  As[ak + 5][ar] = a1.y;
        As[ak + 6][ar] = a1.z;  As[ak + 7][ar] = a1.w;
        *(float4*)(&Bs[bk][bn]) = bv;
        __syncthreads();

        const int kn = k0 + BK;
        if (kn < kend) {   // prefetch next tile while computing
            a0 = *(const float4*)(A + (row0 + ar) * K + kn + ak);
            a1 = *(const float4*)(A + (row0 + ar) * K + kn + ak + 4);
            bv = *(const float4*)(B + (kn + bk) * N + col0 + bn);
        }

        #pragma unroll
        for (int kk = 0; kk < BK; ++kk) {
            const float4 av0 = *(const float4*)(&As[kk][ty << 3]);
            const float4 av1 = *(const float4*)(&As[kk][(ty << 3) + 4]);
            const float4 b   = *(const float4*)(&Bs[kk][tx << 2]);
            acc[0][0] = fmaf(av0.x, b.x, acc[0][0]);
            acc[0][1] = fmaf(av0.x, b.y, acc[0][1]);
            acc[0][2] = fmaf(av0.x, b.z, acc[0][2]);
            acc[0][3] = fmaf(av0.x, b.w, acc[0][3]);
            acc[1][0] = fmaf(av0.y, b.x, acc[1][0]);
            acc[1][1] = fmaf(av0.y, b.y, acc[1][1]);
            acc[1][2] = fmaf(av0.y, b.z, acc[1][2]);
            acc[1][3] = fmaf(av0.y, b.w, acc[1][3]);
            acc[2][0] = fmaf(av0.z, b.x, acc[2][0]);
            acc[2][1] = fmaf(av0.z, b.y, acc[2][1]);
            acc[2][2] = fmaf(av0.z, b.z, acc[2][2]);
            acc[2][3] = fmaf(av0.z, b.w, acc[2][3]);
            acc[3][0] = fmaf(av0.w, b.x, acc[3][0]);
            acc[3][1] = fmaf(av0.w, b.y, acc[3][1]);
            acc[3][2] = fmaf(av0.w, b.z, acc[3][2]);
            acc[3][3] = fmaf(av0.w, b.w, acc[3][3]);
            acc[4][0] = fmaf(av1.x, b.x, acc[4][0]);
            acc[4][1] = fmaf(av1.x, b.y, acc[4][1]);
            acc[4][2] = fmaf(av1.x, b.z, acc[4][2]);
            acc[4][3] = fmaf(av1.x, b.w, acc[4][3]);
            acc[5][0] = fmaf(av1.y, b.x, acc[5][0]);
            acc[5][1] = fmaf(av1.y, b.y, acc[5][1]);
            acc[5][2] = fmaf(av1.y, b.z, acc[5][2]);
            acc[5][3] = fmaf(av1.y, b.w, acc[5][3]);
            acc[6][0] = fmaf(av1.z, b.x, acc[6][0]);
            acc[6][1] = fmaf(av1.z, b.y, acc[6][1]);
            acc[6][2] = fmaf(av1.z, b.z, acc[6][2]);
            acc[6][3] = fmaf(av1.z, b.w, acc[6][3]);
            acc[7][0] = fmaf(av1.w, b.x, acc[7][0]);
            acc[7][1] = fmaf(av1.w, b.y, acc[7][1]);
            acc[7][2] = fmaf(av1.w, b.z, acc[7][2]);
            acc[7][3] = fmaf(av1.w, b.w, acc[7][3]);
        }
        __syncthreads();
    }

    float* Pout = P + blockIdx.z * M * N;
    #pragma unroll
    for (int i = 0; i < 8; ++i) {
        float4 o;
        o.x = acc[i][0]; o.y = acc[i][1]; o.z = acc[i][2]; o.w = acc[i][3];
        *(float4*)(Pout + (row0 + (ty << 3) + i) * N + col0 + (tx << 2)) = o;
    }
}

// ---------------------------------------------------------------------------
// Fused split-K reduce + bias + LIF scan. ILP version: accumulate all 32
// t-sums into registers first (S*32 independent loads), then LIF on regs.
// Deterministic (fixed order).
// ---------------------------------------------------------------------------
template<int S>
__global__ void __launch_bounds__(256) k_reduce_lif(
    const float* __restrict__ P, const float* __restrict__ bias,
    float* __restrict__ out, int F)
{
    const int j  = blockIdx.x * blockDim.x + threadIdx.x;
    const int nb = j / F;
    const int f  = j % F;
    const int MN = T_STEPS * N_BATCH * F;
    const int stride_t = N_BATCH * F;

    float acc[T_STEPS];
    const float b = bias[f];
    #pragma unroll
    for (int t = 0; t < T_STEPS; ++t) acc[t] = b;

    #pragma unroll
    for (int s = 0; s < S; ++s) {
        const float* Ps = P + s * MN + nb * F + f;
        #pragma unroll
        for (int t = 0; t < T_STEPS; ++t)
            acc[t] += Ps[t * stride_t];
    }

    float v = 0.0f;
    float* op = out + nb * F + f;
    #pragma unroll
    for (int t = 0; t < T_STEPS; ++t) {
        v = fmaf(acc[t] - v, 0.5f, v);
        const float sp = (v >= 1.0f) ? 1.0f : 0.0f;
        op[t * stride_t] = sp;
        v = (sp != 0.0f) ? 0.0f : v;
    }
}

// ---------------------------------------------------------------------------
// Tail: reduce(S) + bias + LIF + W_out dot + cumsum. ILP load phase, then
// per-t LIF + warp reduce, one barrier, warp-0 cumsum. Deterministic.
// ---------------------------------------------------------------------------
template<int S>
__global__ void __launch_bounds__(256) k_tail(
    const float* __restrict__ P,      // [S][T*N][F2] partials
    const float* __restrict__ bias,   // b_f2
    const float* __restrict__ W_out,  // [F2]
    const float* __restrict__ b_out,  // [1]
    float* __restrict__ out)          // [T,N]
{
    const int nb   = blockIdx.x;
    const int f    = threadIdx.x;
    const int lane = f & 31;
    const int warp = f >> 5;
    const int MN   = T_STEPS * N_BATCH * F2_DIM;
    const int stride_t = N_BATCH * F2_DIM;

    const float b  = bias[f];
    const float w  = W_out[f];
    const float bo = b_out[0];

    float acc[T_STEPS];
    #pragma unroll
    for (int t = 0; t < T_STEPS; ++t) acc[t] = b;
    #pragma unroll
    for (int s = 0; s < S; ++s) {
        const float* Ps = P + s * MN + nb * F2_DIM + f;
        #pragma unroll
        for (int t = 0; t < T_STEPS; ++t)
            acc[t] += Ps[t * stride_t];
    }

    __shared__ float sh[T_STEPS][8];
    float v = 0.0f;
    #pragma unroll
    for (int t = 0; t < T_STEPS; ++t) {
        v = fmaf(acc[t] - v, 0.5f, v);
        const float sp = (v >= 1.0f) ? 1.0f : 0.0f;
        v = (sp != 0.0f) ? 0.0f : v;

        float r = sp * w;
        #pragma unroll
        for (int off = 16; off; off >>= 1)
            r += __shfl_down_sync(0xffffffffu, r, off);
        if (lane == 0) sh[t][warp] = r;
    }
    __syncthreads();

    if (warp == 0) {
        float z = bo;
        #pragma unroll
        for (int w8 = 0; w8 < 8; ++w8) z += sh[lane][w8];
        float a = 0.0f, mine = 0.0f;
        #pragma unroll
        for (int t = 0; t < T_STEPS; ++t) {
            a += __shfl_sync(0xffffffffu, z, t);
            if (lane == t) mine = a;
        }
        out[lane * N_BATCH + nb] = mine;
    }
}

extern "C" void kernel_launch(void* const* d_in, const int* in_sizes, int n_in,
                              void* d_out, int out_size)
{
    const float* x      = (const float*)d_in[0];
    const float* W_sdc  = (const float*)d_in[1];
    const float* b_sdc  = (const float*)d_in[2];
    const float* w_syn  = (const float*)d_in[3];
    const float* W_pool = (const float*)d_in[4];
    const float* b_pool = (const float*)d_in[5];
    const float* W_f1   = (const float*)d_in[6];
    const float* b_f1   = (const float*)d_in[7];
    const float* W_f2   = (const float*)d_in[8];
    const float* b_f2   = (const float*)d_in[9];
    const float* W_out  = (const float*)d_in[10];
    const float* b_out  = (const float*)d_in[11];
    float* out = (float*)d_out;

    float* s2 = nullptr; float* h1 = nullptr; float* part = nullptr;
    cudaGetSymbolAddress((void**)&s2, g_s2);
    cudaGetSymbolAddress((void**)&h1, g_h1);
    cudaGetSymbolAddress((void**)&part, g_part);

    const int M = T_STEPS * N_BATCH;  // 512

    // K1: fused SNN core -> g_s2 [T,N,D]
    k_snn_core<<<N_BATCH * D_DIM, 256>>>(x, W_sdc, b_sdc, w_syn, W_pool, b_pool);

    // K2: partials of s2 @ W_f1  (M=512, K=256, N=512), S=8, Kc=32 -> 256 blocks
    {
        dim3 grid(F1_DIM / 64, M / 128, 8);
        k_gemm_splitk<<<grid, 256>>>(s2, W_f1, part, M, D_DIM, F1_DIM, 32);
    }
    // K3: reduce(8) + bias + LIF -> h1
    k_reduce_lif<8><<<(N_BATCH * F1_DIM) / 256, 256>>>(part, b_f1, h1, F1_DIM);

    // K4: partials of h1 @ W_f2  (M=512, K=512, N=256), S=8, Kc=64 -> 128 blocks
    {
        dim3 grid(F2_DIM / 64, M / 128, 8);
        k_gemm_splitk<<<grid, 256>>>(h1, W_f2, part, M, F1_DIM, F2_DIM, 64);
    }
    // K5: fused reduce(8) + LIF + readout dot + cumsum -> out
    k_tail<8><<<N_BATCH, 256>>>(part, b_f2, W_out, b_out, out);
}

// round 11
// speedup vs baseline: 1.1096x; 1.1096x over previous
#include <cuda_runtime.h>
#include <math.h>

#define T_STEPS 32
#define N_BATCH 16
#define D_DIM   256
#define A_DIM   256
#define F1_DIM  512
#define F2_DIM  256
#define BK 16

// Scratch (allocation-free rule: __device__ globals)
__device__ float g_s2[T_STEPS * N_BATCH * D_DIM];    // [T,N,D]   512KB
__device__ float g_h1[T_STEPS * N_BATCH * F1_DIM];   // [T,N,F1]  1MB
__device__ float g_part[9 * 256 * 1024];             // split-K partials, 9MB

// ---------------------------------------------------------------------------
// K1: fused SDC-linear + exp-filter + LIF + synapse-filter + pool + s2-LIF.
// R9 design + x preloaded to smem (hot loop does LDS broadcast, not LDG).
// ---------------------------------------------------------------------------
__global__ void __launch_bounds__(256) k_snn_core(
    const float* __restrict__ x,      // [T,N,2,D]
    const float* __restrict__ W_sdc,  // [2,A]
    const float* __restrict__ b_sdc,  // [A]
    const float* __restrict__ w_syn,  // [1]
    const float* __restrict__ W_pool, // [A,1]
    const float* __restrict__ b_pool) // [1]
{
    const int a    = threadIdx.x;
    const int nd   = blockIdx.x;
    const int n    = nd >> 8;   // D = 256
    const int d    = nd & 255;
    const int lane = a & 31;
    const int warp = a >> 5;

    __shared__ float xs[T_STEPS * 2];    // x[t,n,c,d] for this (n,d)
    __shared__ float sh[T_STEPS][137];   // stride 137: conflict-free both phases

    if (a < 64) {
        const int t = a >> 1, c = a & 1;
        xs[a] = x[((t * N_BATCH + n) * 2 + c) * D_DIM + d];
    }

    const float w0 = W_sdc[a];
    const float w1 = W_sdc[A_DIM + a];
    const float ba = b_sdc[a];
    const float wp = W_pool[a];
    const float dsyn = 1.0f - 1.0f / (1.0f + expf(-w_syn[0]));
    const float bp = b_pool[0];

    float i_s = 0.0f, v = 0.0f, syn = 0.0f;
    __syncthreads();

    #pragma unroll 4
    for (int t = 0; t < T_STEPS; ++t) {
        const float x0 = xs[t * 2 + 0];
        const float x1 = xs[t * 2 + 1];
        const float h  = fmaf(x0, w0, fmaf(x1, w1, ba));

        i_s = fmaf(i_s, 0.5f, h);                     // exp_filter tau=2
        v = fmaf(i_s - v, 0.5f, v);                   // LIF tau=2
        const float s1 = (v >= 1.0f) ? 1.0f : 0.0f;
        v = (s1 != 0.0f) ? 0.0f : v;
        syn = fmaf(syn, dsyn, s1);                    // synapse filter

        float val = syn * wp;
        val += __shfl_down_sync(0xffffffffu, val, 16);
        if (lane < 16) sh[t][(warp << 4) + lane] = val;   // 16 partials/warp
    }
    __syncthreads();

    if (warp == 0) {
        float z0 = 0.0f, z1 = 0.0f, z2 = 0.0f, z3 = 0.0f;
        #pragma unroll
        for (int j = 0; j < 128; j += 4) {
            z0 += sh[lane][j + 0];
            z1 += sh[lane][j + 1];
            z2 += sh[lane][j + 2];
            z3 += sh[lane][j + 3];
        }
        float z = bp + ((z0 + z1) + (z2 + z3));

        float v2 = 0.0f, s_mine = 0.0f;
        #pragma unroll
        for (int t = 0; t < T_STEPS; ++t) {
            const float zt = __shfl_sync(0xffffffffu, z, t);
            v2 = fmaf(zt - v2, 0.5f, v2);
            const float s = (v2 >= 1.0f) ? 1.0f : 0.0f;
            v2 = (s != 0.0f) ? 0.0f : v2;
            if (lane == t) s_mine = s;
        }
        g_s2[(lane * N_BATCH + n) * D_DIM + d] = s_mine;
    }
}

// ---------------------------------------------------------------------------
// K2 GEMM: 64(M) x 128(N) tile, BK=16, 256 threads, 8x4 micro-tile.
// Per kk per thread: 3 LDS.128 per 32 FMA AND 256-block grid AND 8 warps.
// Global->reg prefetch. Deterministic.
// ---------------------------------------------------------------------------
__global__ void __launch_bounds__(256) k_gemm_splitk_w(
    const float* __restrict__ A, const float* __restrict__ B,
    float* __restrict__ P, int M, int K, int N, int Kc)
{
    __shared__ float As[BK][68];    // [k][m] 64 + pad
    __shared__ float Bs[BK][132];   // [k][n] 128 + pad
    const int tid = threadIdx.x;
    const int tx  = tid & 31;      // col group (4 cols): 32*4 = 128
    const int ty  = tid >> 5;      // row group (8 rows): 8*8 = 64
    const int row0 = blockIdx.y * 64;
    const int col0 = blockIdx.x * 128;
    const int kbeg = blockIdx.z * Kc;
    const int kend = kbeg + Kc;

    // A: 64 rows x 16 k = 1024 floats -> 1 float4/thread
    const int ar = tid >> 2;             // 0..63
    const int ak = (tid & 3) << 2;       // 0,4,8,12
    // B: 16 k x 128 n = 2048 floats -> 2 float4/thread
    const int bk = tid >> 4;             // 0..15
    const int bn = (tid & 15) << 3;      // 0,8,...,120

    float acc[8][4] = {};

    float4 av  = *(const float4*)(A + (row0 + ar) * K + kbeg + ak);
    float4 bv0 = *(const float4*)(B + (kbeg + bk) * N + col0 + bn);
    float4 bv1 = *(const float4*)(B + (kbeg + bk) * N + col0 + bn + 4);

    for (int k0 = kbeg; k0 < kend; k0 += BK) {
        As[ak + 0][ar] = av.x;
        As[ak + 1][ar] = av.y;
        As[ak + 2][ar] = av.z;
        As[ak + 3][ar] = av.w;
        *(float4*)(&Bs[bk][bn])     = bv0;
        *(float4*)(&Bs[bk][bn + 4]) = bv1;
        __syncthreads();

        const int kn = k0 + BK;
        if (kn < kend) {
            av  = *(const float4*)(A + (row0 + ar) * K + kn + ak);
            bv0 = *(const float4*)(B + (kn + bk) * N + col0 + bn);
            bv1 = *(const float4*)(B + (kn + bk) * N + col0 + bn + 4);
        }

        #pragma unroll
        for (int kk = 0; kk < BK; ++kk) {
            const float4 a0 = *(const float4*)(&As[kk][ty << 3]);
            const float4 a1 = *(const float4*)(&As[kk][(ty << 3) + 4]);
            const float4 b  = *(const float4*)(&Bs[kk][tx << 2]);
            acc[0][0] = fmaf(a0.x, b.x, acc[0][0]);
            acc[0][1] = fmaf(a0.x, b.y, acc[0][1]);
            acc[0][2] = fmaf(a0.x, b.z, acc[0][2]);
            acc[0][3] = fmaf(a0.x, b.w, acc[0][3]);
            acc[1][0] = fmaf(a0.y, b.x, acc[1][0]);
            acc[1][1] = fmaf(a0.y, b.y, acc[1][1]);
            acc[1][2] = fmaf(a0.y, b.z, acc[1][2]);
            acc[1][3] = fmaf(a0.y, b.w, acc[1][3]);
            acc[2][0] = fmaf(a0.z, b.x, acc[2][0]);
            acc[2][1] = fmaf(a0.z, b.y, acc[2][1]);
            acc[2][2] = fmaf(a0.z, b.z, acc[2][2]);
            acc[2][3] = fmaf(a0.z, b.w, acc[2][3]);
            acc[3][0] = fmaf(a0.w, b.x, acc[3][0]);
            acc[3][1] = fmaf(a0.w, b.y, acc[3][1]);
            acc[3][2] = fmaf(a0.w, b.z, acc[3][2]);
            acc[3][3] = fmaf(a0.w, b.w, acc[3][3]);
            acc[4][0] = fmaf(a1.x, b.x, acc[4][0]);
            acc[4][1] = fmaf(a1.x, b.y, acc[4][1]);
            acc[4][2] = fmaf(a1.x, b.z, acc[4][2]);
            acc[4][3] = fmaf(a1.x, b.w, acc[4][3]);
            acc[5][0] = fmaf(a1.y, b.x, acc[5][0]);
            acc[5][1] = fmaf(a1.y, b.y, acc[5][1]);
            acc[5][2] = fmaf(a1.y, b.z, acc[5][2]);
            acc[5][3] = fmaf(a1.y, b.w, acc[5][3]);
            acc[6][0] = fmaf(a1.z, b.x, acc[6][0]);
            acc[6][1] = fmaf(a1.z, b.y, acc[6][1]);
            acc[6][2] = fmaf(a1.z, b.z, acc[6][2]);
            acc[6][3] = fmaf(a1.z, b.w, acc[6][3]);
            acc[7][0] = fmaf(a1.w, b.x, acc[7][0]);
            acc[7][1] = fmaf(a1.w, b.y, acc[7][1]);
            acc[7][2] = fmaf(a1.w, b.z, acc[7][2]);
            acc[7][3] = fmaf(a1.w, b.w, acc[7][3]);
        }
        __syncthreads();
    }

    float* Pout = P + blockIdx.z * M * N;
    #pragma unroll
    for (int i = 0; i < 8; ++i) {
        float4 o;
        o.x = acc[i][0]; o.y = acc[i][1]; o.z = acc[i][2]; o.w = acc[i][3];
        *(float4*)(Pout + (row0 + (ty << 3) + i) * N + col0 + (tx << 2)) = o;
    }
}

// ---------------------------------------------------------------------------
// K4 GEMM: R9 64x64 tile, 256 threads, 4x4 micro (measured 9.2us). Deterministic.
// ---------------------------------------------------------------------------
__global__ void __launch_bounds__(256) k_gemm_splitk(
    const float* __restrict__ A, const float* __restrict__ B,
    float* __restrict__ P, int M, int K, int N, int Kc)
{
    __shared__ float As[BK][68];
    __shared__ float Bs[BK][64];
    const int tid = threadIdx.x;
    const int tx  = tid & 15;
    const int ty  = tid >> 4;
    const int row0 = blockIdx.y * 64;
    const int col0 = blockIdx.x * 64;
    const int kbeg = blockIdx.z * Kc;
    const int kend = kbeg + Kc;

    const int ar = tid >> 2;
    const int ak = (tid & 3) << 2;
    const int bk = tid >> 4;
    const int bn = (tid & 15) << 2;

    float acc[4][4] = {};

    float4 av = *(const float4*)(A + (row0 + ar) * K + kbeg + ak);
    float4 bv = *(const float4*)(B + (kbeg + bk) * N + col0 + bn);

    for (int k0 = kbeg; k0 < kend; k0 += BK) {
        As[ak + 0][ar] = av.x;
        As[ak + 1][ar] = av.y;
        As[ak + 2][ar] = av.z;
        As[ak + 3][ar] = av.w;
        *(float4*)(&Bs[bk][bn]) = bv;
        __syncthreads();

        const int kn = k0 + BK;
        if (kn < kend) {
            av = *(const float4*)(A + (row0 + ar) * K + kn + ak);
            bv = *(const float4*)(B + (kn + bk) * N + col0 + bn);
        }

        #pragma unroll
        for (int kk = 0; kk < BK; ++kk) {
            const float4 a = *(const float4*)(&As[kk][ty << 2]);
            const float4 b = *(const float4*)(&Bs[kk][tx << 2]);
            acc[0][0] = fmaf(a.x, b.x, acc[0][0]);
            acc[0][1] = fmaf(a.x, b.y, acc[0][1]);
            acc[0][2] = fmaf(a.x, b.z, acc[0][2]);
            acc[0][3] = fmaf(a.x, b.w, acc[0][3]);
            acc[1][0] = fmaf(a.y, b.x, acc[1][0]);
            acc[1][1] = fmaf(a.y, b.y, acc[1][1]);
            acc[1][2] = fmaf(a.y, b.z, acc[1][2]);
            acc[1][3] = fmaf(a.y, b.w, acc[1][3]);
            acc[2][0] = fmaf(a.z, b.x, acc[2][0]);
            acc[2][1] = fmaf(a.z, b.y, acc[2][1]);
            acc[2][2] = fmaf(a.z, b.z, acc[2][2]);
            acc[2][3] = fmaf(a.z, b.w, acc[2][3]);
            acc[3][0] = fmaf(a.w, b.x, acc[3][0]);
            acc[3][1] = fmaf(a.w, b.y, acc[3][1]);
            acc[3][2] = fmaf(a.w, b.z, acc[3][2]);
            acc[3][3] = fmaf(a.w, b.w, acc[3][3]);
        }
        __syncthreads();
    }

    float* Pout = P + blockIdx.z * M * N;
    #pragma unroll
    for (int i = 0; i < 4; ++i) {
        float4 o;
        o.x = acc[i][0]; o.y = acc[i][1]; o.z = acc[i][2]; o.w = acc[i][3];
        *(float4*)(Pout + (row0 + (ty << 2) + i) * N + col0 + (tx << 2)) = o;
    }
}

// ---------------------------------------------------------------------------
// Fused split-K reduce + bias + LIF scan. ILP: all t-sums in registers first.
// ---------------------------------------------------------------------------
template<int S>
__global__ void __launch_bounds__(256) k_reduce_lif(
    const float* __restrict__ P, const float* __restrict__ bias,
    float* __restrict__ out, int F)
{
    const int j  = blockIdx.x * blockDim.x + threadIdx.x;
    const int nb = j / F;
    const int f  = j % F;
    const int MN = T_STEPS * N_BATCH * F;
    const int stride_t = N_BATCH * F;

    float acc[T_STEPS];
    const float b = bias[f];
    #pragma unroll
    for (int t = 0; t < T_STEPS; ++t) acc[t] = b;

    #pragma unroll
    for (int s = 0; s < S; ++s) {
        const float* Ps = P + s * MN + nb * F + f;
        #pragma unroll
        for (int t = 0; t < T_STEPS; ++t)
            acc[t] += Ps[t * stride_t];
    }

    float v = 0.0f;
    float* op = out + nb * F + f;
    #pragma unroll
    for (int t = 0; t < T_STEPS; ++t) {
        v = fmaf(acc[t] - v, 0.5f, v);
        const float sp = (v >= 1.0f) ? 1.0f : 0.0f;
        op[t * stride_t] = sp;
        v = (sp != 0.0f) ? 0.0f : v;
    }
}

// ---------------------------------------------------------------------------
// Tail: reduce(S) + bias + LIF + W_out dot + cumsum. ILP load phase.
// ---------------------------------------------------------------------------
template<int S>
__global__ void __launch_bounds__(256) k_tail(
    const float* __restrict__ P, const float* __restrict__ bias,
    const float* __restrict__ W_out, const float* __restrict__ b_out,
    float* __restrict__ out)
{
    const int nb   = blockIdx.x;
    const int f    = threadIdx.x;
    const int lane = f & 31;
    const int warp = f >> 5;
    const int MN   = T_STEPS * N_BATCH * F2_DIM;
    const int stride_t = N_BATCH * F2_DIM;

    const float b  = bias[f];
    const float w  = W_out[f];
    const float bo = b_out[0];

    float acc[T_STEPS];
    #pragma unroll
    for (int t = 0; t < T_STEPS; ++t) acc[t] = b;
    #pragma unroll
    for (int s = 0; s < S; ++s) {
        const float* Ps = P + s * MN + nb * F2_DIM + f;
        #pragma unroll
        for (int t = 0; t < T_STEPS; ++t)
            acc[t] += Ps[t * stride_t];
    }

    __shared__ float sh[T_STEPS][8];
    float v = 0.0f;
    #pragma unroll
    for (int t = 0; t < T_STEPS; ++t) {
        v = fmaf(acc[t] - v, 0.5f, v);
        const float sp = (v >= 1.0f) ? 1.0f : 0.0f;
        v = (sp != 0.0f) ? 0.0f : v;

        float r = sp * w;
        #pragma unroll
        for (int off = 16; off; off >>= 1)
            r += __shfl_down_sync(0xffffffffu, r, off);
        if (lane == 0) sh[t][warp] = r;
    }
    __syncthreads();

    if (warp == 0) {
        float z = bo;
        #pragma unroll
        for (int w8 = 0; w8 < 8; ++w8) z += sh[lane][w8];
        float a = 0.0f, mine = 0.0f;
        #pragma unroll
        for (int t = 0; t < T_STEPS; ++t) {
            a += __shfl_sync(0xffffffffu, z, t);
            if (lane == t) mine = a;
        }
        out[lane * N_BATCH + nb] = mine;
    }
}

extern "C" void kernel_launch(void* const* d_in, const int* in_sizes, int n_in,
                              void* d_out, int out_size)
{
    const float* x      = (const float*)d_in[0];
    const float* W_sdc  = (const float*)d_in[1];
    const float* b_sdc  = (const float*)d_in[2];
    const float* w_syn  = (const float*)d_in[3];
    const float* W_pool = (const float*)d_in[4];
    const float* b_pool = (const float*)d_in[5];
    const float* W_f1   = (const float*)d_in[6];
    const float* b_f1   = (const float*)d_in[7];
    const float* W_f2   = (const float*)d_in[8];
    const float* b_f2   = (const float*)d_in[9];
    const float* W_out  = (const float*)d_in[10];
    const float* b_out  = (const float*)d_in[11];
    float* out = (float*)d_out;

    float* s2 = nullptr; float* h1 = nullptr; float* part = nullptr;
    cudaGetSymbolAddress((void**)&s2, g_s2);
    cudaGetSymbolAddress((void**)&h1, g_h1);
    cudaGetSymbolAddress((void**)&part, g_part);

    const int M = T_STEPS * N_BATCH;  // 512

    // K1: fused SNN core -> g_s2 [T,N,D]
    k_snn_core<<<N_BATCH * D_DIM, 256>>>(x, W_sdc, b_sdc, w_syn, W_pool, b_pool);

    // K2: partials of s2 @ W_f1  (M=512, K=256, N=512), S=8, Kc=32 -> 256 blocks
    {
        dim3 grid(F1_DIM / 128, M / 64, 8);
        k_gemm_splitk_w<<<grid, 256>>>(s2, W_f1, part, M, D_DIM, F1_DIM, 32);
    }
    // K3: reduce(8) + bias + LIF -> h1
    k_reduce_lif<8><<<(N_BATCH * F1_DIM) / 256, 256>>>(part, b_f1, h1, F1_DIM);

    // K4: partials of h1 @ W_f2  (M=512, K=512, N=256), S=8, Kc=64 -> 256 blocks
    {
        dim3 grid(F2_DIM / 64, M / 64, 8);
        k_gemm_splitk<<<grid, 256>>>(h1, W_f2, part, M, F1_DIM, F2_DIM, 64);
    }
    // K5: fused reduce(8) + LIF + readout dot + cumsum -> out
    k_tail<8><<<N_BATCH, 256>>>(part, b_f2, W_out, b_out, out);
}